// round 10
// baseline (speedup 1.0000x reference)
#include <cuda_runtime.h>

#define NN   16384
#define EE   524288
#define DIN  256
#define DOUT 128
#define X_ELEMS (NN * DOUT)

#define NGEMMB   256       // blocks 0..255 do the GEMM (64 rows each)
#define NCLAIMS  16384     // 16384 claims x 64KB = 1,073,741,824 B = all of A
#define CLAIM_F4 4096      // 64KB per claim

// Scratch (no allocations allowed). g_zctr/g_done reset by scatter each launch.
__device__ float    g_s[EE];
__device__ float    g_ssum[NN];
__device__ int      g_cnt[NN];
__device__ float    g_sq[NN];
__device__ unsigned g_zctr;
__device__ unsigned g_done;

// Fused: zero(A) at the HBM store floor from t=0, with the GEMM (blocks 0-255)
// and the per-edge gather phase hidden underneath it.
__global__ __launch_bounds__(256, 4) void fused_kernel(const float* __restrict__ In,
                                                       const float* __restrict__ W,
                                                       const int* __restrict__ edge,
                                                       const float* __restrict__ a,
                                                       float* __restrict__ X,
                                                       float* __restrict__ A) {
    __shared__ float Ast[32][68];    // A tile k-major transposed, 16B-aligned rows
    __shared__ float Bs[32][128];
    __shared__ float ssq[64];
    __shared__ unsigned s_c;

    const int tid = threadIdx.x;
    const int bid = blockIdx.x;
    float4* A4 = reinterpret_cast<float4*>(A);
    const float4 z4 = make_float4(0.f, 0.f, 0.f, 0.f);

    if (bid < NGEMMB) {
        // ---------------- GEMM: rows bid*64 .. +63 ----------------
        const int brow = bid * 64;
        const int tx = tid & 15;     // cols tx*8..+7
        const int ty = tid >> 4;     // rows ty*4..+3

        if (tid < 64) {
            g_ssum[brow + tid] = 0.0f;
            g_cnt[brow + tid]  = 0;
            ssq[tid] = 0.0f;
        }
        float acc[4][8];
#pragma unroll
        for (int i = 0; i < 4; i++)
#pragma unroll
            for (int j = 0; j < 8; j++) acc[i][j] = 0.0f;

        for (int k0 = 0; k0 < DIN; k0 += 32) {
#pragma unroll
            for (int i = 0; i < 2; i++) {       // A: 64x32 = 512 f4
                int f  = tid + i * 256;
                int r  = f >> 3;
                int c4 = f & 7;
                float4 v = *(const float4*)(In + (size_t)(brow + r) * DIN + k0 + c4 * 4);
                Ast[c4 * 4 + 0][r] = v.x;
                Ast[c4 * 4 + 1][r] = v.y;
                Ast[c4 * 4 + 2][r] = v.z;
                Ast[c4 * 4 + 3][r] = v.w;
            }
#pragma unroll
            for (int i = 0; i < 4; i++) {       // B: 32x128 = 1024 f4
                int f = tid + i * 256;
                int r = f >> 5;
                int c = (f & 31) * 4;
                *(float4*)&Bs[r][c] = *(const float4*)(W + (size_t)(k0 + r) * DOUT + c);
            }
            __syncthreads();
#pragma unroll 4
            for (int k = 0; k < 32; k++) {
                float4 av4 = *(float4*)&Ast[k][ty * 4];
                float4 b0  = *(float4*)&Bs[k][tx * 8];
                float4 b1  = *(float4*)&Bs[k][tx * 8 + 4];
                float aa[4] = {av4.x, av4.y, av4.z, av4.w};
                float bb[8] = {b0.x, b0.y, b0.z, b0.w, b1.x, b1.y, b1.z, b1.w};
#pragma unroll
                for (int i = 0; i < 4; i++)
#pragma unroll
                    for (int j = 0; j < 8; j++)
                        acc[i][j] = fmaf(aa[i], bb[j], acc[i][j]);
            }
            __syncthreads();
        }
#pragma unroll
        for (int i = 0; i < 4; i++) {
            int r = brow + ty * 4 + i;
            float4 o0 = {acc[i][0], acc[i][1], acc[i][2], acc[i][3]};
            float4 o1 = {acc[i][4], acc[i][5], acc[i][6], acc[i][7]};
            *(float4*)(X + (size_t)r * DOUT + tx * 8)     = o0;
            *(float4*)(X + (size_t)r * DOUT + tx * 8 + 4) = o1;
            float p = acc[i][0]*acc[i][0] + acc[i][1]*acc[i][1] + acc[i][2]*acc[i][2] + acc[i][3]*acc[i][3]
                    + acc[i][4]*acc[i][4] + acc[i][5]*acc[i][5] + acc[i][6]*acc[i][6] + acc[i][7]*acc[i][7];
            atomicAdd(&ssq[ty * 4 + i], p);
        }
        __syncthreads();
        if (tid < 64) g_sq[brow + tid] = ssq[tid];
        __threadfence();
        __syncthreads();
        if (tid == 0) atomicAdd(&g_done, 1);
    } else {
        // -------- zero A from the claim queue until the GEMM finishes --------
        for (;;) {
            if (tid == 0) {
                unsigned f = *(volatile unsigned*)&g_done;
                s_c = (f >= NGEMMB) ? 0xFFFFFFFFu : atomicAdd(&g_zctr, 1);
            }
            __syncthreads();
            unsigned c = s_c;
            __syncthreads();
            if (c >= NCLAIMS) break;   // flag set or queue empty
            float4* dst = A4 + (size_t)c * CLAIM_F4;
#pragma unroll
            for (int i = 0; i < 16; i++)
                __stcs(dst + tid + i * 256, z4);
        }
    }

    // -------- wait for GEMM completion (usually already done) --------
    if (tid == 0) {
        while (*(volatile unsigned*)&g_done < NGEMMB) __nanosleep(64);
    }
    __syncthreads();
    __threadfence();

    // -------- gather phase: one warp per edge, 8 edges per block --------
    {
        int e    = bid * 8 + (tid >> 5);
        int lane = tid & 31;
        int row = edge[e];
        int col = edge[EE + e];

        float4 xi = *(const float4*)(X + (size_t)row * DOUT + lane * 4);
        float4 xj = *(const float4*)(X + (size_t)col * DOUT + lane * 4);
        float4 av = *(const float4*)(a + lane * 4);

        float t = fmaxf(xi.x * xj.x, 0.0f) * av.x
                + fmaxf(xi.y * xj.y, 0.0f) * av.y
                + fmaxf(xi.z * xj.z, 0.0f) * av.z
                + fmaxf(xi.w * xj.w, 0.0f) * av.w;
#pragma unroll
        for (int o = 16; o; o >>= 1) t += __shfl_down_sync(0xffffffffu, t, o);

        if (lane == 0) {
            // s bounded by ||a||_2 (~1.4) => exp cannot overflow; max-shift redundant.
            float ex = 0.0f;
            if (t > 0.0f) ex = __expf(t * rsqrtf(g_sq[row] * g_sq[col]));
            g_s[e] = ex;
            atomicAdd(&g_ssum[row], ex);
            atomicAdd(&g_cnt[row], 1);
        }
    }

    // -------- drain the remaining zero queue --------
    for (;;) {
        if (tid == 0) s_c = atomicAdd(&g_zctr, 1);
        __syncthreads();
        unsigned c = s_c;
        __syncthreads();
        if (c >= NCLAIMS) break;
        float4* dst = A4 + (size_t)c * CLAIM_F4;
#pragma unroll
        for (int i = 0; i < 16; i++)
            __stcs(dst + tid + i * 256, z4);
    }
}

// vals = ex / ssum[row] (or 1/cnt for all-gated rows); scatter-add into A.
// Also resets queue + flag for the next graph replay.
__global__ void scatter_kernel(const int* __restrict__ edge, float* __restrict__ A) {
    if (blockIdx.x == 0 && threadIdx.x == 0) { g_zctr = 0; g_done = 0; }
    int e = blockIdx.x * blockDim.x + threadIdx.x;
    if (e >= EE) return;
    int row = edge[e];
    int col = edge[EE + e];
    float denom = g_ssum[row];
    float v = (denom > 0.0f) ? (g_s[e] / denom) : (1.0f / (float)g_cnt[row]);
    atomicAdd(A + (size_t)row * NN + col, v);
}

extern "C" void kernel_launch(void* const* d_in, const int* in_sizes, int n_in,
                              void* d_out, int out_size) {
    const float* In   = (const float*)d_in[0];   // [16384, 256]
    const int*   edge = (const int*)d_in[1];     // [2, 524288]
    const float* W    = (const float*)d_in[2];   // [256, 128]
    const float* a    = (const float*)d_in[3];   // [128, 1]
    float* X = (float*)d_out;                    // [16384, 128]
    float* A = X + X_ELEMS;                      // [16384, 16384]

    fused_kernel<<<EE / 8, 256>>>(In, W, edge, a, X, A);
    scatter_kernel<<<EE / 256, 256>>>(edge, A);
}

// round 12
// speedup vs baseline: 1.4926x; 1.4926x over previous
#include <cuda_runtime.h>

#define NN   16384
#define EE   524288
#define DIN  256
#define DOUT 128
#define X_ELEMS (NN * DOUT)

#define NGEMMB    256     // fused bids 0..255 do the GEMM (64 rows each)
#define NEARLY    640     // first 640 row-blocks carry extra zero duty
#define NEXTRA    23      // extras per early block: 640*23 = 14720 tail rows
#define TAIL0     1664    // tail region rows [1664, 16384): zeroed by early blocks

// Scratch (no allocations allowed). All rewritten every launch.
__device__ int      g_rowcnt[NN];
__device__ int      g_rowptr[NN + 1];
__device__ int      g_rowcur[NN];
__device__ int      g_scol[EE];      // edge cols, sorted by row
__device__ float    g_s[EE];         // per-edge exp(s), CSR order
__device__ float    g_sq[NN];        // per-row squared L2 norm of x
__device__ unsigned g_done;          // gemm-complete counter
__device__ unsigned g_zdone;         // early-zone zero-duty counter

// ---- K0: reset scratch ----
__global__ void init_kernel() {
    int i = blockIdx.x * blockDim.x + threadIdx.x;
    if (i < NN) g_rowcnt[i] = 0;
    if (i == 0) { g_done = 0; g_zdone = 0; }
}

// ---- K1: histogram of rows ----
__global__ void hist_kernel(const int* __restrict__ edge) {
    int e = blockIdx.x * blockDim.x + threadIdx.x;
    if (e < EE) atomicAdd(&g_rowcnt[edge[e]], 1);
}

// ---- K2: exclusive prefix sum (single block, 1024 threads x 16 rows) ----
__global__ __launch_bounds__(1024) void prefix_kernel() {
    __shared__ int ps[1024];
    int t = threadIdx.x;
    int base = t * 16;
    int loc[16];
    int s = 0;
#pragma unroll
    for (int i = 0; i < 16; i++) { loc[i] = g_rowcnt[base + i]; s += loc[i]; }
    ps[t] = s;
    __syncthreads();
    for (int off = 1; off < 1024; off <<= 1) {
        int v = (t >= off) ? ps[t - off] : 0;
        __syncthreads();
        ps[t] += v;
        __syncthreads();
    }
    int run = ps[t] - s;   // exclusive prefix for this thread's chunk
#pragma unroll
    for (int i = 0; i < 16; i++) {
        g_rowptr[base + i] = run;
        g_rowcur[base + i] = run;
        run += loc[i];
    }
    if (t == 1023) g_rowptr[NN] = run;
}

// ---- K3: scatter edges into CSR order ----
__global__ void sortsc_kernel(const int* __restrict__ edge) {
    int e = blockIdx.x * blockDim.x + threadIdx.x;
    if (e >= EE) return;
    int row = edge[e];
    int col = edge[EE + e];
    int pos = atomicAdd(&g_rowcur[row], 1);
    g_scol[pos] = col;
}

// zero one 64KB row of A (4096 float4 by 256 threads)
__device__ __forceinline__ void zero_row(float4* __restrict__ A4, int row, int tid) {
    float4* dst = A4 + (size_t)row * (NN / 4);
    const float4 z = make_float4(0.f, 0.f, 0.f, 0.f);
#pragma unroll
    for (int i = 0; i < 16; i++)
        __stcs(dst + tid + i * 256, z);
}

// ---- K4: fused gemm + zero(A) + per-row softmax + scatter ----
__global__ __launch_bounds__(256, 4) void fused_kernel(const float* __restrict__ In,
                                                       const float* __restrict__ W,
                                                       const float* __restrict__ a,
                                                       float* __restrict__ X,
                                                       float* __restrict__ A) {
    const int tid = threadIdx.x;
    const int bid = blockIdx.x;

    if (bid < NGEMMB) {
        // -------- GEMM: rows bid*64 .. +63 (hidden under the store stream) ----
        __shared__ __align__(16) float Ast[32][68];
        __shared__ __align__(16) float Bs[32][128];
        __shared__ float ssq[64];
        const int brow = bid * 64;
        const int tx = tid & 15;
        const int ty = tid >> 4;
        if (tid < 64) ssq[tid] = 0.0f;

        float acc[4][8];
#pragma unroll
        for (int i = 0; i < 4; i++)
#pragma unroll
            for (int j = 0; j < 8; j++) acc[i][j] = 0.0f;

        for (int k0 = 0; k0 < DIN; k0 += 32) {
#pragma unroll
            for (int i = 0; i < 2; i++) {
                int f  = tid + i * 256;
                int r  = f >> 3;
                int c4 = f & 7;
                float4 v = *(const float4*)(In + (size_t)(brow + r) * DIN + k0 + c4 * 4);
                Ast[c4 * 4 + 0][r] = v.x;
                Ast[c4 * 4 + 1][r] = v.y;
                Ast[c4 * 4 + 2][r] = v.z;
                Ast[c4 * 4 + 3][r] = v.w;
            }
#pragma unroll
            for (int i = 0; i < 4; i++) {
                int f = tid + i * 256;
                int r = f >> 5;
                int c = (f & 31) * 4;
                *(float4*)&Bs[r][c] = *(const float4*)(W + (size_t)(k0 + r) * DOUT + c);
            }
            __syncthreads();
#pragma unroll 4
            for (int k = 0; k < 32; k++) {
                float4 a4 = *(float4*)&Ast[k][ty * 4];
                float4 b0 = *(float4*)&Bs[k][tx * 8];
                float4 b1 = *(float4*)&Bs[k][tx * 8 + 4];
                float aa[4] = {a4.x, a4.y, a4.z, a4.w};
                float bb[8] = {b0.x, b0.y, b0.z, b0.w, b1.x, b1.y, b1.z, b1.w};
#pragma unroll
                for (int i = 0; i < 4; i++)
#pragma unroll
                    for (int j = 0; j < 8; j++)
                        acc[i][j] = fmaf(aa[i], bb[j], acc[i][j]);
            }
            __syncthreads();
        }
#pragma unroll
        for (int i = 0; i < 4; i++) {
            int r = brow + ty * 4 + i;
            float4 o0 = {acc[i][0], acc[i][1], acc[i][2], acc[i][3]};
            float4 o1 = {acc[i][4], acc[i][5], acc[i][6], acc[i][7]};
            *(float4*)(X + (size_t)r * DOUT + tx * 8)     = o0;
            *(float4*)(X + (size_t)r * DOUT + tx * 8 + 4) = o1;
            float p = acc[i][0]*acc[i][0] + acc[i][1]*acc[i][1] + acc[i][2]*acc[i][2] + acc[i][3]*acc[i][3]
                    + acc[i][4]*acc[i][4] + acc[i][5]*acc[i][5] + acc[i][6]*acc[i][6] + acc[i][7]*acc[i][7];
            atomicAdd(&ssq[ty * 4 + i], p);
        }
        __syncthreads();
        if (tid < 64) g_sq[brow + tid] = ssq[tid];
        __threadfence();
        __syncthreads();
        if (tid == 0) atomicAdd(&g_done, 1);
        return;
    }

    // -------- Row block: owns row r --------
    const int r = bid - NGEMMB;
    float4* A4 = reinterpret_cast<float4*>(A);

    if (r < NEARLY) {
        // early zone: zero own row + NEXTRA tail rows (keeps stores at the
        // floor while the GEMM runs)
        zero_row(A4, r, tid);
        int t0 = TAIL0 + r * NEXTRA;
#pragma unroll 1
        for (int j = 0; j < NEXTRA; j++)
            zero_row(A4, t0 + j, tid);
        __threadfence();
        __syncthreads();
        if (tid == 0) atomicAdd(&g_zdone, 1);
    } else if (r < TAIL0) {
        zero_row(A4, r, tid);
        __threadfence();   // order own-row zeros before vals atomics below
    } else {
        // tail: row zeroed by an early block; wait for that duty to finish
        if (tid == 0) {
            while (*(volatile unsigned*)&g_zdone < NEARLY) __nanosleep(128);
        }
    }

    // wait for GEMM (X, g_sq)
    if (tid == 0) {
        while (*(volatile unsigned*)&g_done < NGEMMB) __nanosleep(128);
    }
    __syncthreads();
    __threadfence();

    const int p0  = g_rowptr[r];
    const int deg = g_rowptr[r + 1] - p0;
    if (deg == 0) return;

    __shared__ __align__(16) float xi_s[DOUT];
    __shared__ __align__(16) float a_s[DOUT];
    __shared__ float wsum[8];
    __shared__ float s_tot;
    if (tid < 32) {
        *(float4*)&xi_s[tid * 4] = *(const float4*)(X + (size_t)r * DOUT + tid * 4);
        *(float4*)&a_s[tid * 4]  = *(const float4*)(a + tid * 4);
    }
    if (tid < 8) wsum[tid] = 0.0f;
    __syncthreads();

    const int wid  = tid >> 5;
    const int lane = tid & 31;
    const float sqi = g_sq[r];
    float lsum = 0.0f;

    for (int k = wid; k < deg; k += 8) {
        int col = g_scol[p0 + k];
        float4 xj = *(const float4*)(X + (size_t)col * DOUT + lane * 4);
        float4 xi = *(const float4*)&xi_s[lane * 4];
        float4 av = *(const float4*)&a_s[lane * 4];
        float t = fmaxf(xi.x * xj.x, 0.0f) * av.x
                + fmaxf(xi.y * xj.y, 0.0f) * av.y
                + fmaxf(xi.z * xj.z, 0.0f) * av.z
                + fmaxf(xi.w * xj.w, 0.0f) * av.w;
#pragma unroll
        for (int o = 16; o; o >>= 1) t += __shfl_down_sync(0xffffffffu, t, o);
        if (lane == 0) {
            // s bounded by ||a||_2 (~1.4) => exp cannot overflow; max-shift
            // redundant. Gated edges contribute 0; all-gated rows use 1/deg.
            float ex = 0.0f;
            if (t > 0.0f) ex = __expf(t * rsqrtf(sqi * g_sq[col]));
            g_s[p0 + k] = ex;
            lsum += ex;
        }
    }
    if (lane == 0) atomicAdd(&wsum[wid], lsum);   // smem atomic, cheap
    __threadfence_block();
    __syncthreads();
    if (tid == 0) s_tot = wsum[0] + wsum[1] + wsum[2] + wsum[3]
                        + wsum[4] + wsum[5] + wsum[6] + wsum[7];
    __syncthreads();

    const float tot = s_tot;
    const float inv = (tot > 0.0f) ? (1.0f / tot) : 0.0f;
    const float fb  = 1.0f / (float)deg;
    for (int k = tid; k < deg; k += 256) {
        float v = (tot > 0.0f) ? (g_s[p0 + k] * inv) : fb;
        atomicAdd(A + (size_t)r * NN + g_scol[p0 + k], v);   // duplicates accumulate
    }
}

extern "C" void kernel_launch(void* const* d_in, const int* in_sizes, int n_in,
                              void* d_out, int out_size) {
    const float* In   = (const float*)d_in[0];   // [16384, 256]
    const int*   edge = (const int*)d_in[1];     // [2, 524288]
    const float* W    = (const float*)d_in[2];   // [256, 128]
    const float* a    = (const float*)d_in[3];   // [128, 1]
    float* X = (float*)d_out;                    // [16384, 128]
    float* A = X + X_ELEMS;                      // [16384, 16384]

    init_kernel<<<16, 1024>>>();
    hist_kernel<<<512, 1024>>>(edge);
    prefix_kernel<<<1, 1024>>>();
    sortsc_kernel<<<512, 1024>>>(edge);
    fused_kernel<<<NGEMMB + NN, 256>>>(In, W, a, X, A);
}

// round 13
// speedup vs baseline: 2.6174x; 1.7536x over previous
#include <cuda_runtime.h>

#define NN   16384
#define EE   524288
#define DIN  256
#define DOUT 128
#define X_ELEMS (NN * DOUT)

// score zeroes ALL of A: 65536 blocks x 1024 f4 = 67,108,864 f4 = 1073 MB.
#define SCORE_Z_F4_PER_BLOCK 1024

// Scratch (no allocations allowed).
__device__ float g_s[EE];      // per-edge exp(s)
__device__ float g_ssum[NN];   // per-row sum of exp(s)
__device__ int   g_cnt[NN];    // per-row edge count (degenerate-row fallback)
__device__ float g_sq[NN];     // per-row squared L2 norm of x

// x = In[16384,256] @ W[256,128]. 64x128 block tile, 4x8 register tile per
// thread, 256 blocks (>148 SMs, ~3 blocks/SM co-resident) — fixes the
// grid-starved occupancy of the 128-block version. Also zeroes ssum/cnt and
// computes per-row squared norms.
__global__ __launch_bounds__(256) void gemm_kernel(const float* __restrict__ In,
                                                   const float* __restrict__ W,
                                                   float* __restrict__ X) {
    __shared__ __align__(16) float Ast[32][68];   // A tile k-major transposed
    __shared__ __align__(16) float Bs[32][128];   // B tile
    __shared__ float ssq[64];

    const int tid  = threadIdx.x;
    const int brow = blockIdx.x * 64;
    const int tx   = tid & 15;       // cols tx*8 .. +7
    const int ty   = tid >> 4;       // rows ty*4 .. +3

    if (tid < 64) {
        g_ssum[brow + tid] = 0.0f;
        g_cnt[brow + tid]  = 0;
        ssq[tid] = 0.0f;
    }

    float acc[4][8];
#pragma unroll
    for (int i = 0; i < 4; i++)
#pragma unroll
        for (int j = 0; j < 8; j++) acc[i][j] = 0.0f;

    for (int k0 = 0; k0 < DIN; k0 += 32) {
#pragma unroll
        for (int i = 0; i < 2; i++) {       // A: 64x32 = 512 f4, 2 per thread
            int f  = tid + i * 256;
            int r  = f >> 3;
            int c4 = f & 7;
            float4 v = *(const float4*)(In + (size_t)(brow + r) * DIN + k0 + c4 * 4);
            Ast[c4 * 4 + 0][r] = v.x;
            Ast[c4 * 4 + 1][r] = v.y;
            Ast[c4 * 4 + 2][r] = v.z;
            Ast[c4 * 4 + 3][r] = v.w;
        }
#pragma unroll
        for (int i = 0; i < 4; i++) {       // B: 32x128 = 1024 f4, 4 per thread
            int f = tid + i * 256;
            int r = f >> 5;
            int c = (f & 31) * 4;
            *(float4*)&Bs[r][c] = *(const float4*)(W + (size_t)(k0 + r) * DOUT + c);
        }
        __syncthreads();
#pragma unroll 4
        for (int k = 0; k < 32; k++) {
            float4 a4 = *(float4*)&Ast[k][ty * 4];
            float4 b0 = *(float4*)&Bs[k][tx * 8];
            float4 b1 = *(float4*)&Bs[k][tx * 8 + 4];
            float aa[4] = {a4.x, a4.y, a4.z, a4.w};
            float bb[8] = {b0.x, b0.y, b0.z, b0.w, b1.x, b1.y, b1.z, b1.w};
#pragma unroll
            for (int i = 0; i < 4; i++)
#pragma unroll
                for (int j = 0; j < 8; j++)
                    acc[i][j] = fmaf(aa[i], bb[j], acc[i][j]);
        }
        __syncthreads();
    }

#pragma unroll
    for (int i = 0; i < 4; i++) {
        int r = brow + ty * 4 + i;
        float4 o0 = {acc[i][0], acc[i][1], acc[i][2], acc[i][3]};
        float4 o1 = {acc[i][4], acc[i][5], acc[i][6], acc[i][7]};
        *(float4*)(X + (size_t)r * DOUT + tx * 8)     = o0;
        *(float4*)(X + (size_t)r * DOUT + tx * 8 + 4) = o1;
        float p = acc[i][0]*acc[i][0] + acc[i][1]*acc[i][1] + acc[i][2]*acc[i][2] + acc[i][3]*acc[i][3]
                + acc[i][4]*acc[i][4] + acc[i][5]*acc[i][5] + acc[i][6]*acc[i][6] + acc[i][7]*acc[i][7];
        atomicAdd(&ssq[ty * 4 + i], p);
    }
    __syncthreads();
    if (tid < 64) g_sq[brow + tid] = ssq[tid];
}

// Per-edge: ex = exp(dot(relu(xi*xj),a) * rsqrt(sq_i*sq_j)) if dot>0 else 0.
// s bounded by ||a||_2 (~1.4) => exp cannot overflow; max-shift redundant.
// One warp per edge. Zeroes 16KB of A per block (4 streaming stores/thread) —
// overlaps the L2-latency-bound gathers; kernel sits at the HBM store floor.
__global__ __launch_bounds__(256) void score_kernel(const float* __restrict__ X,
                                                    const int* __restrict__ edge,
                                                    const float* __restrict__ a,
                                                    float* __restrict__ A) {
    {
        float4 z4 = make_float4(0.f, 0.f, 0.f, 0.f);
        float4* zdst = reinterpret_cast<float4*>(A)
                     + (size_t)blockIdx.x * SCORE_Z_F4_PER_BLOCK;
#pragma unroll
        for (int i = 0; i < 4; i++)
            __stcs(zdst + threadIdx.x + i * 256, z4);
    }

    int e    = (int)((blockIdx.x * 256u + threadIdx.x) >> 5);
    int lane = threadIdx.x & 31;
    if (e >= EE) return;
    int row = edge[e];
    int col = edge[EE + e];

    float4 xi = *(const float4*)(X + (size_t)row * DOUT + lane * 4);
    float4 xj = *(const float4*)(X + (size_t)col * DOUT + lane * 4);
    float4 av = *(const float4*)(a + lane * 4);

    float t = fmaxf(xi.x * xj.x, 0.0f) * av.x
            + fmaxf(xi.y * xj.y, 0.0f) * av.y
            + fmaxf(xi.z * xj.z, 0.0f) * av.z
            + fmaxf(xi.w * xj.w, 0.0f) * av.w;
#pragma unroll
    for (int o = 16; o; o >>= 1) t += __shfl_down_sync(0xffffffffu, t, o);

    if (lane == 0) {
        float ex = 0.0f;
        if (t > 0.0f) ex = __expf(t * rsqrtf(g_sq[row] * g_sq[col]));
        g_s[e] = ex;
        atomicAdd(&g_ssum[row], ex);
        atomicAdd(&g_cnt[row], 1);
    }
}

// vals = ex / ssum[row] (or 1/cnt for all-gated rows); scatter-add into A.
__global__ void scatter_kernel(const int* __restrict__ edge, float* __restrict__ A) {
    int e = blockIdx.x * blockDim.x + threadIdx.x;
    if (e >= EE) return;
    int row = edge[e];
    int col = edge[EE + e];
    float denom = g_ssum[row];
    float v = (denom > 0.0f) ? (g_s[e] / denom) : (1.0f / (float)g_cnt[row]);
    atomicAdd(A + (size_t)row * NN + col, v);
}

extern "C" void kernel_launch(void* const* d_in, const int* in_sizes, int n_in,
                              void* d_out, int out_size) {
    const float* In   = (const float*)d_in[0];   // [16384, 256]
    const int*   edge = (const int*)d_in[1];     // [2, 524288]
    const float* W    = (const float*)d_in[2];   // [256, 128]
    const float* a    = (const float*)d_in[3];   // [128, 1]
    float* X = (float*)d_out;                    // [16384, 128]
    float* A = X + X_ELEMS;                      // [16384, 16384]

    gemm_kernel<<<NN / 64, 256>>>(In, W, X);
    score_kernel<<<EE / 8, 256>>>(X, edge, a, A);
    scatter_kernel<<<EE / 256, 256>>>(edge, A);
}

// round 14
// speedup vs baseline: 2.6318x; 1.0055x over previous
#include <cuda_runtime.h>

#define NN   16384
#define EE   524288
#define DIN  256
#define DOUT 128
#define X_ELEMS (NN * DOUT)

// A = 67,108,864 float4 (1073 MB).
// gemm zeroes blocks 0..127 x 65536 f4 = 8,388,608 f4 (128 MB), trickled
// through the k-loop (8 iters x 8192 f4/block).
// score zeroes the rest: 65536 blocks x 896 f4 = 58,720,256 f4 (945 MB).
#define GEMM_Z_F4_PER_BLOCK  65536
#define GEMM_Z_F4_PER_ITER   8192
#define SCORE_Z_F4_PER_BLOCK 896
#define SCORE_Z_OFF_F4       8388608

// Scratch (no allocations allowed).
__device__ float g_s[EE];      // per-edge exp(s)
__device__ float g_ssum[NN];   // per-row sum of exp(s)
__device__ int   g_cnt[NN];    // per-row edge count (degenerate-row fallback)
__device__ float g_sq[NN];     // per-row squared L2 norm of x

// x = In[16384,256] @ W[256,128]. 128x128 block tile, 8x8 register tile
// (FFMA-bound; best measured config, 41.9us). The otherwise-idle store pipe
// carries a trickle of A-zeroing: 32 streaming f4 stores per thread per
// k-iteration, interleaved with the FMA stream (no burst stall).
__global__ __launch_bounds__(256) void gemm_kernel(const float* __restrict__ In,
                                                   const float* __restrict__ W,
                                                   float* __restrict__ X,
                                                   float* __restrict__ A) {
    __shared__ __align__(16) float Ast[32][132];  // A tile, k-major transposed
    __shared__ __align__(16) float Bs[32][128];   // B tile
    __shared__ float ssq[128];

    const int tid  = threadIdx.x;
    const int brow = blockIdx.x * 128;
    const int tx   = tid & 15;
    const int ty   = tid >> 4;

    float4* zdst = reinterpret_cast<float4*>(A)
                 + (size_t)blockIdx.x * GEMM_Z_F4_PER_BLOCK;
    const float4 z4 = make_float4(0.f, 0.f, 0.f, 0.f);

    if (tid < 128) {
        g_ssum[brow + tid] = 0.0f;
        g_cnt[brow + tid]  = 0;
        ssq[tid] = 0.0f;
    }

    float acc[8][8];
#pragma unroll
    for (int i = 0; i < 8; i++)
#pragma unroll
        for (int j = 0; j < 8; j++) acc[i][j] = 0.0f;

    for (int k0 = 0; k0 < DIN; k0 += 32) {
#pragma unroll
        for (int i = 0; i < 4; i++) {
            int f  = tid + i * 256;
            int r  = f >> 3;
            int c4 = f & 7;
            float4 v = *(const float4*)(In + (size_t)(brow + r) * DIN + k0 + c4 * 4);
            Ast[c4 * 4 + 0][r] = v.x;
            Ast[c4 * 4 + 1][r] = v.y;
            Ast[c4 * 4 + 2][r] = v.z;
            Ast[c4 * 4 + 3][r] = v.w;
        }
#pragma unroll
        for (int i = 0; i < 4; i++) {
            int f = tid + i * 256;
            int r = f >> 5;
            int c = (f & 31) * 4;
            *(float4*)&Bs[r][c] = *(const float4*)(W + (size_t)(k0 + r) * DOUT + c);
        }
        __syncthreads();

        // trickle-zero: 32 fire-and-forget streaming stores; the FFMA stream
        // below executes while these drain through the store pipe.
        {
            float4* zd = zdst + (k0 >> 5) * GEMM_Z_F4_PER_ITER + tid;
#pragma unroll
            for (int i = 0; i < 32; i++)
                __stcs(zd + i * 256, z4);
        }

#pragma unroll 4
        for (int k = 0; k < 32; k++) {
            float4 a0 = *(float4*)&Ast[k][ty * 8];
            float4 a1 = *(float4*)&Ast[k][ty * 8 + 4];
            float4 b0 = *(float4*)&Bs[k][tx * 8];
            float4 b1 = *(float4*)&Bs[k][tx * 8 + 4];
            float a[8] = {a0.x, a0.y, a0.z, a0.w, a1.x, a1.y, a1.z, a1.w};
            float b[8] = {b0.x, b0.y, b0.z, b0.w, b1.x, b1.y, b1.z, b1.w};
#pragma unroll
            for (int i = 0; i < 8; i++)
#pragma unroll
                for (int j = 0; j < 8; j++)
                    acc[i][j] = fmaf(a[i], b[j], acc[i][j]);
        }
        __syncthreads();
    }

#pragma unroll
    for (int i = 0; i < 8; i++) {
        int r = brow + ty * 8 + i;
        float4 o0 = {acc[i][0], acc[i][1], acc[i][2], acc[i][3]};
        float4 o1 = {acc[i][4], acc[i][5], acc[i][6], acc[i][7]};
        *(float4*)(X + (size_t)r * DOUT + tx * 8)     = o0;
        *(float4*)(X + (size_t)r * DOUT + tx * 8 + 4) = o1;
        float p = acc[i][0]*acc[i][0] + acc[i][1]*acc[i][1] + acc[i][2]*acc[i][2] + acc[i][3]*acc[i][3]
                + acc[i][4]*acc[i][4] + acc[i][5]*acc[i][5] + acc[i][6]*acc[i][6] + acc[i][7]*acc[i][7];
        atomicAdd(&ssq[ty * 8 + i], p);
    }
    __syncthreads();
    if (tid < 128) g_sq[brow + tid] = ssq[tid];
}

// Per-edge: ex = exp(dot(relu(xi*xj),a) * rsqrt(sq_i*sq_j)) if dot>0 else 0.
// s bounded by ||a||_2 (~1.4) => exp cannot overflow; max-shift redundant.
// One warp per edge. Zeroes 14KB of A per block (streaming stores) — overlaps
// the L2-latency-bound gathers; kernel sits at the (reduced) HBM store floor.
__global__ __launch_bounds__(256) void score_kernel(const float* __restrict__ X,
                                                    const int* __restrict__ edge,
                                                    const float* __restrict__ a,
                                                    float* __restrict__ A) {
    {
        float4 z4 = make_float4(0.f, 0.f, 0.f, 0.f);
        float4* zdst = reinterpret_cast<float4*>(A) + SCORE_Z_OFF_F4
                     + (size_t)blockIdx.x * SCORE_Z_F4_PER_BLOCK;
#pragma unroll
        for (int i = threadIdx.x; i < SCORE_Z_F4_PER_BLOCK; i += 256)
            __stcs(zdst + i, z4);
    }

    int e    = (int)((blockIdx.x * 256u + threadIdx.x) >> 5);
    int lane = threadIdx.x & 31;
    if (e >= EE) return;
    int row = edge[e];
    int col = edge[EE + e];

    float4 xi = *(const float4*)(X + (size_t)row * DOUT + lane * 4);
    float4 xj = *(const float4*)(X + (size_t)col * DOUT + lane * 4);
    float4 av = *(const float4*)(a + lane * 4);

    float t = fmaxf(xi.x * xj.x, 0.0f) * av.x
            + fmaxf(xi.y * xj.y, 0.0f) * av.y
            + fmaxf(xi.z * xj.z, 0.0f) * av.z
            + fmaxf(xi.w * xj.w, 0.0f) * av.w;
#pragma unroll
    for (int o = 16; o; o >>= 1) t += __shfl_down_sync(0xffffffffu, t, o);

    if (lane == 0) {
        float ex = 0.0f;
        if (t > 0.0f) ex = __expf(t * rsqrtf(g_sq[row] * g_sq[col]));
        g_s[e] = ex;
        atomicAdd(&g_ssum[row], ex);
        atomicAdd(&g_cnt[row], 1);
    }
}

// vals = ex / ssum[row] (or 1/cnt for all-gated rows); scatter-add into A.
__global__ void scatter_kernel(const int* __restrict__ edge, float* __restrict__ A) {
    int e = blockIdx.x * blockDim.x + threadIdx.x;
    if (e >= EE) return;
    int row = edge[e];
    int col = edge[EE + e];
    float denom = g_ssum[row];
    float v = (denom > 0.0f) ? (g_s[e] / denom) : (1.0f / (float)g_cnt[row]);
    atomicAdd(A + (size_t)row * NN + col, v);
}

extern "C" void kernel_launch(void* const* d_in, const int* in_sizes, int n_in,
                              void* d_out, int out_size) {
    const float* In   = (const float*)d_in[0];   // [16384, 256]
    const int*   edge = (const int*)d_in[1];     // [2, 524288]
    const float* W    = (const float*)d_in[2];   // [256, 128]
    const float* a    = (const float*)d_in[3];   // [128, 1]
    float* X = (float*)d_out;                    // [16384, 128]
    float* A = X + X_ELEMS;                      // [16384, 16384]

    gemm_kernel<<<NN / 128, 256>>>(In, W, X, A);
    score_kernel<<<EE / 8, 256>>>(X, edge, a, A);
    scatter_kernel<<<EE / 256, 256>>>(edge, A);
}

// round 15
// speedup vs baseline: 2.6609x; 1.0110x over previous
#include <cuda_runtime.h>

#define NN   16384
#define EE   524288
#define DIN  256
#define DOUT 128
#define X_ELEMS (NN * DOUT)

// score zeroes ALL of A: 65536 blocks x 1024 f4 = 67,108,864 f4 = 1073 MB.
#define SCORE_Z_F4_PER_BLOCK 1024

// Scratch (no allocations allowed).
__device__ float g_s[EE];      // per-edge exp(s)
__device__ float g_ssum[NN];   // per-row sum of exp(s)
__device__ int   g_cnt[NN];    // per-row edge count (degenerate-row fallback)
__device__ float g_sq[NN];     // per-row squared L2 norm of x

// x = In[16384,256] @ W[256,128]. 64x128 block tile with 128 threads and an
// 8x8 register tile per thread (ratio 4 FMA/LDS-float, same inner pattern as
// the 41.9us config) -> grid 256 blocks, multiple blocks/SM co-resident to
// cover syncthreads + smem latency. Also zeroes ssum/cnt, computes sq norms.
__global__ __launch_bounds__(128) void gemm_kernel(const float* __restrict__ In,
                                                   const float* __restrict__ W,
                                                   float* __restrict__ X) {
    __shared__ __align__(16) float Ast[32][68];   // A tile, k-major transposed
    __shared__ __align__(16) float Bs[32][128];   // B tile
    __shared__ float ssq[64];

    const int tid  = threadIdx.x;                 // 0..127
    const int brow = blockIdx.x * 64;
    const int tx   = tid & 15;                    // cols tx*8 .. +7
    const int ty   = tid >> 4;                    // 0..7, rows ty*8 .. +7

    if (tid < 64) {
        g_ssum[brow + tid] = 0.0f;
        g_cnt[brow + tid]  = 0;
        ssq[tid] = 0.0f;
    }

    float acc[8][8];
#pragma unroll
    for (int i = 0; i < 8; i++)
#pragma unroll
        for (int j = 0; j < 8; j++) acc[i][j] = 0.0f;

    for (int k0 = 0; k0 < DIN; k0 += 32) {
        // A tile: 64 rows x 32 k = 512 f4, 4 per thread, stored transposed.
#pragma unroll
        for (int i = 0; i < 4; i++) {
            int f  = tid + i * 128;
            int r  = f >> 3;          // 0..63
            int c4 = f & 7;           // 0..7
            float4 v = *(const float4*)(In + (size_t)(brow + r) * DIN + k0 + c4 * 4);
            Ast[c4 * 4 + 0][r] = v.x;
            Ast[c4 * 4 + 1][r] = v.y;
            Ast[c4 * 4 + 2][r] = v.z;
            Ast[c4 * 4 + 3][r] = v.w;
        }
        // B tile: 32 k x 128 cols = 1024 f4, 8 per thread.
#pragma unroll
        for (int i = 0; i < 8; i++) {
            int f = tid + i * 128;
            int r = f >> 5;           // 0..31
            int c = (f & 31) * 4;
            *(float4*)&Bs[r][c] = *(const float4*)(W + (size_t)(k0 + r) * DOUT + c);
        }
        __syncthreads();
#pragma unroll 4
        for (int k = 0; k < 32; k++) {
            float4 a0 = *(float4*)&Ast[k][ty * 8];
            float4 a1 = *(float4*)&Ast[k][ty * 8 + 4];
            float4 b0 = *(float4*)&Bs[k][tx * 8];
            float4 b1 = *(float4*)&Bs[k][tx * 8 + 4];
            float a[8] = {a0.x, a0.y, a0.z, a0.w, a1.x, a1.y, a1.z, a1.w};
            float b[8] = {b0.x, b0.y, b0.z, b0.w, b1.x, b1.y, b1.z, b1.w};
#pragma unroll
            for (int i = 0; i < 8; i++)
#pragma unroll
                for (int j = 0; j < 8; j++)
                    acc[i][j] = fmaf(a[i], b[j], acc[i][j]);
        }
        __syncthreads();
    }

#pragma unroll
    for (int i = 0; i < 8; i++) {
        int r = brow + ty * 8 + i;
        float4 o0 = {acc[i][0], acc[i][1], acc[i][2], acc[i][3]};
        float4 o1 = {acc[i][4], acc[i][5], acc[i][6], acc[i][7]};
        *(float4*)(X + (size_t)r * DOUT + tx * 8)     = o0;
        *(float4*)(X + (size_t)r * DOUT + tx * 8 + 4) = o1;
        float p = acc[i][0]*acc[i][0] + acc[i][1]*acc[i][1] + acc[i][2]*acc[i][2] + acc[i][3]*acc[i][3]
                + acc[i][4]*acc[i][4] + acc[i][5]*acc[i][5] + acc[i][6]*acc[i][6] + acc[i][7]*acc[i][7];
        atomicAdd(&ssq[ty * 8 + i], p);
    }
    __syncthreads();
    if (tid < 64) g_sq[brow + tid] = ssq[tid];
}

// Per-edge: ex = exp(dot(relu(xi*xj),a) * rsqrt(sq_i*sq_j)) if dot>0 else 0.
// s bounded by ||a||_2 (~1.4) => exp cannot overflow; max-shift redundant.
// One warp per edge. Zeroes 16KB of A per block (4 streaming stores/thread) —
// overlaps the L2-latency-bound gathers; kernel sits at the HBM store floor.
__global__ __launch_bounds__(256) void score_kernel(const float* __restrict__ X,
                                                    const int* __restrict__ edge,
                                                    const float* __restrict__ a,
                                                    float* __restrict__ A) {
    {
        float4 z4 = make_float4(0.f, 0.f, 0.f, 0.f);
        float4* zdst = reinterpret_cast<float4*>(A)
                     + (size_t)blockIdx.x * SCORE_Z_F4_PER_BLOCK;
#pragma unroll
        for (int i = 0; i < 4; i++)
            __stcs(zdst + threadIdx.x + i * 256, z4);
    }

    int e    = (int)((blockIdx.x * 256u + threadIdx.x) >> 5);
    int lane = threadIdx.x & 31;
    if (e >= EE) return;
    int row = edge[e];
    int col = edge[EE + e];

    float4 xi = *(const float4*)(X + (size_t)row * DOUT + lane * 4);
    float4 xj = *(const float4*)(X + (size_t)col * DOUT + lane * 4);
    float4 av = *(const float4*)(a + lane * 4);

    float t = fmaxf(xi.x * xj.x, 0.0f) * av.x
            + fmaxf(xi.y * xj.y, 0.0f) * av.y
            + fmaxf(xi.z * xj.z, 0.0f) * av.z
            + fmaxf(xi.w * xj.w, 0.0f) * av.w;
#pragma unroll
    for (int o = 16; o; o >>= 1) t += __shfl_down_sync(0xffffffffu, t, o);

    if (lane == 0) {
        float ex = 0.0f;
        if (t > 0.0f) ex = __expf(t * rsqrtf(g_sq[row] * g_sq[col]));
        g_s[e] = ex;
        atomicAdd(&g_ssum[row], ex);
        atomicAdd(&g_cnt[row], 1);
    }
}

// vals = ex / ssum[row] (or 1/cnt for all-gated rows); scatter-add into A.
__global__ void scatter_kernel(const int* __restrict__ edge, float* __restrict__ A) {
    int e = blockIdx.x * blockDim.x + threadIdx.x;
    if (e >= EE) return;
    int row = edge[e];
    int col = edge[EE + e];
    float denom = g_ssum[row];
    float v = (denom > 0.0f) ? (g_s[e] / denom) : (1.0f / (float)g_cnt[row]);
    atomicAdd(A + (size_t)row * NN + col, v);
}

extern "C" void kernel_launch(void* const* d_in, const int* in_sizes, int n_in,
                              void* d_out, int out_size) {
    const float* In   = (const float*)d_in[0];   // [16384, 256]
    const int*   edge = (const int*)d_in[1];     // [2, 524288]
    const float* W    = (const float*)d_in[2];   // [256, 128]
    const float* a    = (const float*)d_in[3];   // [128, 1]
    float* X = (float*)d_out;                    // [16384, 128]
    float* A = X + X_ELEMS;                      // [16384, 16384]

    gemm_kernel<<<NN / 64, 128>>>(In, W, X);
    score_kernel<<<EE / 8, 256>>>(X, edge, a, A);
    scatter_kernel<<<EE / 256, 256>>>(edge, A);
}

// round 16
// speedup vs baseline: 2.7528x; 1.0345x over previous
#include <cuda_runtime.h>

#define NN   16384
#define EE   524288
#define DIN  256
#define DOUT 128
#define X_ELEMS (NN * DOUT)

// score zeroes ALL of A: 65536 blocks x 1024 f4 = 1073 MB.
#define SCORE_Z_F4_PER_BLOCK 1024

// Scratch (no allocations allowed).
__device__ float g_part[2 * NN * DOUT];   // split-K partials (16.8 MB)
__device__ float g_s[EE];
__device__ float g_ssum[NN];
__device__ int   g_cnt[NN];
__device__ float g_sq[NN];

// Split-K GEMM: 256 blocks; block b -> tile (b>>1), K-half (b&1).
// 128x128 tile, 8x8 register tile per thread (known-good ratio-4 inner loop),
// 2 blocks/SM co-resident (~14 warps/SM) to cover smem latency + syncs.
__global__ __launch_bounds__(256) void gemm_split_kernel(const float* __restrict__ In,
                                                         const float* __restrict__ W) {
    __shared__ __align__(16) float Ast[32][132];
    __shared__ __align__(16) float Bs[32][128];

    const int tid  = threadIdx.x;
    const int tile = blockIdx.x >> 1;
    const int kh   = blockIdx.x & 1;
    const int brow = tile * 128;
    const int kbeg = kh * 128;
    const int tx   = tid & 15;
    const int ty   = tid >> 4;

    float acc[8][8];
#pragma unroll
    for (int i = 0; i < 8; i++)
#pragma unroll
        for (int j = 0; j < 8; j++) acc[i][j] = 0.0f;

    for (int k0 = kbeg; k0 < kbeg + 128; k0 += 32) {
#pragma unroll
        for (int i = 0; i < 4; i++) {
            int f  = tid + i * 256;
            int r  = f >> 3;
            int c4 = f & 7;
            float4 v = *(const float4*)(In + (size_t)(brow + r) * DIN + k0 + c4 * 4);
            Ast[c4 * 4 + 0][r] = v.x;
            Ast[c4 * 4 + 1][r] = v.y;
            Ast[c4 * 4 + 2][r] = v.z;
            Ast[c4 * 4 + 3][r] = v.w;
        }
#pragma unroll
        for (int i = 0; i < 4; i++) {
            int f = tid + i * 256;
            int r = f >> 5;
            int c = (f & 31) * 4;
            *(float4*)&Bs[r][c] = *(const float4*)(W + (size_t)(k0 + r) * DOUT + c);
        }
        __syncthreads();
#pragma unroll 4
        for (int k = 0; k < 32; k++) {
            float4 a0 = *(float4*)&Ast[k][ty * 8];
            float4 a1 = *(float4*)&Ast[k][ty * 8 + 4];
            float4 b0 = *(float4*)&Bs[k][tx * 8];
            float4 b1 = *(float4*)&Bs[k][tx * 8 + 4];
            float a[8] = {a0.x, a0.y, a0.z, a0.w, a1.x, a1.y, a1.z, a1.w};
            float b[8] = {b0.x, b0.y, b0.z, b0.w, b1.x, b1.y, b1.z, b1.w};
#pragma unroll
            for (int i = 0; i < 8; i++)
#pragma unroll
                for (int j = 0; j < 8; j++)
                    acc[i][j] = fmaf(a[i], b[j], acc[i][j]);
        }
        __syncthreads();
    }

    float* P = g_part + (size_t)kh * NN * DOUT;
#pragma unroll
    for (int i = 0; i < 8; i++) {
        int r = brow + ty * 8 + i;
        float4 o0 = {acc[i][0], acc[i][1], acc[i][2], acc[i][3]};
        float4 o1 = {acc[i][4], acc[i][5], acc[i][6], acc[i][7]};
        *(float4*)(P + (size_t)r * DOUT + tx * 8)     = o0;
        *(float4*)(P + (size_t)r * DOUT + tx * 8 + 4) = o1;
    }
}

// Combine partials -> X, compute per-row squared norm, init ssum/cnt.
// One warp per row.
__global__ __launch_bounds__(256) void combine_kernel(float* __restrict__ X) {
    int w    = (blockIdx.x * 256 + threadIdx.x) >> 5;   // row
    int lane = threadIdx.x & 31;
    if (w >= NN) return;
    const float* P0 = g_part;
    const float* P1 = g_part + (size_t)NN * DOUT;
    float4 p0 = *(const float4*)(P0 + (size_t)w * DOUT + lane * 4);
    float4 p1 = *(const float4*)(P1 + (size_t)w * DOUT + lane * 4);
    float4 x4 = {p0.x + p1.x, p0.y + p1.y, p0.z + p1.z, p0.w + p1.w};
    *(float4*)(X + (size_t)w * DOUT + lane * 4) = x4;
    float t = x4.x * x4.x + x4.y * x4.y + x4.z * x4.z + x4.w * x4.w;
#pragma unroll
    for (int o = 16; o; o >>= 1) t += __shfl_down_sync(0xffffffffu, t, o);
    if (lane == 0) {
        g_sq[w]   = t;
        g_ssum[w] = 0.0f;
        g_cnt[w]  = 0;
    }
}

// Per-edge: ex = exp(dot(relu(xi*xj),a) * rsqrt(sq_i*sq_j)) if dot>0 else 0.
// s bounded by ||a||_2 (~1.4) => exp cannot overflow; max-shift redundant.
// One warp per edge; zeroes 16KB of A per block (streaming stores hidden
// under the L2-latency-bound gathers) — sits at the HBM store floor.
__global__ __launch_bounds__(256) void score_kernel(const float* __restrict__ X,
                                                    const int* __restrict__ edge,
                                                    const float* __restrict__ a,
                                                    float* __restrict__ A) {
    {
        float4 z4 = make_float4(0.f, 0.f, 0.f, 0.f);
        float4* zdst = reinterpret_cast<float4*>(A)
                     + (size_t)blockIdx.x * SCORE_Z_F4_PER_BLOCK;
#pragma unroll
        for (int i = 0; i < 4; i++)
            __stcs(zdst + threadIdx.x + i * 256, z4);
    }

    int e    = (int)((blockIdx.x * 256u + threadIdx.x) >> 5);
    int lane = threadIdx.x & 31;
    if (e >= EE) return;
    int row = edge[e];
    int col = edge[EE + e];

    float4 xi = *(const float4*)(X + (size_t)row * DOUT + lane * 4);
    float4 xj = *(const float4*)(X + (size_t)col * DOUT + lane * 4);
    float4 av = *(const float4*)(a + lane * 4);

    float t = fmaxf(xi.x * xj.x, 0.0f) * av.x
            + fmaxf(xi.y * xj.y, 0.0f) * av.y
            + fmaxf(xi.z * xj.z, 0.0f) * av.z
            + fmaxf(xi.w * xj.w, 0.0f) * av.w;
#pragma unroll
    for (int o = 16; o; o >>= 1) t += __shfl_down_sync(0xffffffffu, t, o);

    if (lane == 0) {
        float ex = 0.0f;
        if (t > 0.0f) ex = __expf(t * rsqrtf(g_sq[row] * g_sq[col]));
        g_s[e] = ex;
        atomicAdd(&g_ssum[row], ex);
        atomicAdd(&g_cnt[row], 1);
    }
}

// vals = ex / ssum[row] (or 1/cnt); scatter-add into A. 4 edges per thread
// with batched loads (MLP=4) to shorten the latency-bound critical path.
__global__ __launch_bounds__(256) void scatter_kernel(const int* __restrict__ edge,
                                                      float* __restrict__ A) {
    int base = blockIdx.x * 1024 + threadIdx.x;
    int rows[4], cols[4];
    float ex[4];
#pragma unroll
    for (int i = 0; i < 4; i++) {
        rows[i] = edge[base + i * 256];
        cols[i] = edge[EE + base + i * 256];
    }
#pragma unroll
    for (int i = 0; i < 4; i++) ex[i] = g_s[base + i * 256];
#pragma unroll
    for (int i = 0; i < 4; i++) {
        float denom = g_ssum[rows[i]];
        float v = (denom > 0.0f) ? (ex[i] / denom) : (1.0f / (float)g_cnt[rows[i]]);
        atomicAdd(A + (size_t)rows[i] * NN + cols[i], v);
    }
}

extern "C" void kernel_launch(void* const* d_in, const int* in_sizes, int n_in,
                              void* d_out, int out_size) {
    const float* In   = (const float*)d_in[0];   // [16384, 256]
    const int*   edge = (const int*)d_in[1];     // [2, 524288]
    const float* W    = (const float*)d_in[2];   // [256, 128]
    const float* a    = (const float*)d_in[3];   // [128, 1]
    float* X = (float*)d_out;                    // [16384, 128]
    float* A = X + X_ELEMS;                      // [16384, 16384]

    gemm_split_kernel<<<256, 256>>>(In, W);
    combine_kernel<<<NN / 8, 256>>>(X);
    score_kernel<<<EE / 8, 256>>>(X, edge, a, A);
    scatter_kernel<<<EE / 1024, 256>>>(edge, A);
}